// round 11
// baseline (speedup 1.0000x reference)
#include <cuda_runtime.h>
#include <cstdint>
#include <cstddef>

#define BSZ    4
#define GRID_S 64
#define DIM    1024
#define NHEAD  16
#define DHEAD  64
#define NTOK   4096
#define ROWS   (BSZ*NTOK)

// ---------------- scratch ----------------
__device__ __align__(256) float g_norm[(size_t)ROWS*DIM];
__device__ __align__(256) float g_qkv [(size_t)ROWS*3*DIM];
__device__ __align__(256) float g_attn[(size_t)ROWS*DIM];
__device__ __align__(256) float g_res [(size_t)ROWS*DIM];
__device__ __align__(256) float g_out1[(size_t)ROWS*DIM];
__device__ __align__(256) float g_hid [(size_t)ROWS*4*DIM];
__device__ __align__(256) float g_wt  [25165824];   // tf32-rounded, TRANSPOSED [N][K]

#define OFF_QKV 0
#define OFF_WO  3145728
#define OFF_MA  4194304
#define OFF_MB  8388608
#define LAYER_W 12582912

__device__ __forceinline__ uint32_t f2tf(float f) {
    uint32_t r; asm("cvt.rna.tf32.f32 %0, %1;" : "=r"(r) : "f"(f)); return r;
}
__device__ __forceinline__ float f2tf_f(float f) {
    uint32_t r = f2tf(f); return __uint_as_float(r);
}

// ---------------- dummy (profiler alignment: ncu captures 4th launch) ----------------
__global__ void dummy_k(float* p) { if (threadIdx.x == 0) p[0] = 0.f; }

// ---------------- fused transpose + tf32 round (validated round 4) ----------------
struct TransDesc { const float* s; float* d; int K; int N; int t0; };
struct TransArgs { TransDesc w[8]; };

__global__ __launch_bounds__(256) void trans_tf32(TransArgs a)
{
    __shared__ float sm[32][33];
    int bid = blockIdx.x;
    int seg = 0;
    #pragma unroll
    for (int i = 1; i < 8; i++) if (bid >= a.w[i].t0) seg = i;
    const float* src = a.w[seg].s;
    float* dst = a.w[seg].d;
    int K = a.w[seg].K, N = a.w[seg].N;
    int local = bid - a.w[seg].t0;
    int ncols = N >> 5;
    int tr = local / ncols, tc = local - tr * ncols;
    int t = threadIdx.x;
    int r0 = t >> 5, c = t & 31;
    #pragma unroll
    for (int u = 0; u < 4; u++) {
        int k = tr * 32 + r0 + u * 8;
        sm[r0 + u * 8][c] = src[(size_t)k * N + tc * 32 + c];
    }
    __syncthreads();
    #pragma unroll
    for (int u = 0; u < 4; u++) {
        int n = tc * 32 + r0 + u * 8;
        dst[(size_t)n * K + tr * 32 + c] = f2tf_f(sm[c][r0 + u * 8]);
    }
}

// ---------------- LayerNorm (outputs tf32-rounded) ----------------
__global__ __launch_bounds__(256) void ln_kernel(const float* __restrict__ x,
                                                 const float* __restrict__ g,
                                                 const float* __restrict__ b,
                                                 float* __restrict__ y)
{
    int row = blockIdx.x, t = threadIdx.x;
    float4 v = reinterpret_cast<const float4*>(x + (size_t)row * DIM)[t];
    float s = v.x + v.y + v.z + v.w;
    float q = v.x*v.x + v.y*v.y + v.z*v.z + v.w*v.w;
    #pragma unroll
    for (int o = 16; o > 0; o >>= 1) {
        s += __shfl_xor_sync(0xffffffffu, s, o);
        q += __shfl_xor_sync(0xffffffffu, q, o);
    }
    __shared__ float rs_[8], rq_[8];
    __shared__ float s_mu, s_rs;
    if ((t & 31) == 0) { rs_[t>>5] = s; rq_[t>>5] = q; }
    __syncthreads();
    if (t == 0) {
        float S = 0.f, Q = 0.f;
        #pragma unroll
        for (int i = 0; i < 8; i++) { S += rs_[i]; Q += rq_[i]; }
        float mu = S * (1.0f/DIM);
        s_mu = mu;
        s_rs = rsqrtf(Q * (1.0f/DIM) - mu*mu + 1e-5f);
    }
    __syncthreads();
    float mu = s_mu, r = s_rs;
    float4 g4 = reinterpret_cast<const float4*>(g)[t];
    float4 b4 = reinterpret_cast<const float4*>(b)[t];
    float4 o;
    o.x = f2tf_f((v.x-mu)*r*g4.x + b4.x);  o.y = f2tf_f((v.y-mu)*r*g4.y + b4.y);
    o.z = f2tf_f((v.z-mu)*r*g4.z + b4.z);  o.w = f2tf_f((v.w-mu)*r*g4.w + b4.w);
    reinterpret_cast<float4*>(y + (size_t)row * DIM)[t] = o;
}

// ---------------- TF32 GEMM v11: mbarrier pipeline (noinc fix), no in-loop __syncthreads ----------------
#define GBM 128
#define GBN 128
#define GBK 32
#define A_STAGE (GBM*GBK)             // 4096 floats = 16KB
#define B_STAGE (GBN*GBK)             // 4096 floats = 16KB
#define NSTG 3
#define GEMM_SMEM (NSTG*(A_STAGE+B_STAGE)*4)   // 96KB -> 2 CTAs/SM

__device__ __forceinline__ void ldsm4(uint32_t& r0, uint32_t& r1, uint32_t& r2, uint32_t& r3, uint32_t a) {
    asm volatile("ldmatrix.sync.aligned.m8n8.x4.shared.b16 {%0,%1,%2,%3}, [%4];"
                 : "=r"(r0), "=r"(r1), "=r"(r2), "=r"(r3) : "r"(a));
}
__device__ __forceinline__ void mma_tf32(float* c, const uint32_t* a, const uint32_t* b) {
    asm volatile("mma.sync.aligned.m16n8k8.row.col.f32.tf32.tf32.f32 "
                 "{%0,%1,%2,%3}, {%4,%5,%6,%7}, {%8,%9}, {%0,%1,%2,%3};"
                 : "+f"(c[0]), "+f"(c[1]), "+f"(c[2]), "+f"(c[3])
                 : "r"(a[0]), "r"(a[1]), "r"(a[2]), "r"(a[3]), "r"(b[0]), "r"(b[1]));
}
__device__ __forceinline__ void cp16(uint32_t dst, const float* src) {
    asm volatile("cp.async.cg.shared.global [%0], [%1], 16;" :: "r"(dst), "l"(src));
}
__device__ __forceinline__ void mbar_init(uint32_t a, uint32_t cnt) {
    asm volatile("mbarrier.init.shared.b64 [%0], %1;" :: "r"(a), "r"(cnt) : "memory");
}
__device__ __forceinline__ void mbar_arrive(uint32_t a) {
    asm volatile("mbarrier.arrive.shared.b64 _, [%0];" :: "r"(a) : "memory");
}
__device__ __forceinline__ void cp_arrive(uint32_t a) {
    // .noinc: the deferred arrive counts against the init count (default form
    // pre-increments pending count and self-cancels -> deadlock).
    asm volatile("cp.async.mbarrier.arrive.noinc.shared.b64 [%0];" :: "r"(a) : "memory");
}
__device__ __forceinline__ void mbar_wait_acq(uint32_t a, uint32_t parity) {
    asm volatile("{\n\t.reg .pred P1;\n"
        "LAB_%=:\n\t"
        "mbarrier.try_wait.parity.acquire.cta.shared::cta.b64 P1, [%0], %1;\n\t"
        "@!P1 bra LAB_%=;\n\t}"
        :: "r"(a), "r"(parity) : "memory");
}
__device__ __forceinline__ void mbar_wait_rlx(uint32_t a, uint32_t parity) {
    asm volatile("{\n\t.reg .pred P1;\n"
        "LAB_%=:\n\t"
        "mbarrier.try_wait.parity.relaxed.cta.shared::cta.b64 P1, [%0], %1;\n\t"
        "@!P1 bra LAB_%=;\n\t}"
        :: "r"(a), "r"(parity) : "memory");
}

template <bool RES, bool RND>
__global__ __launch_bounds__(256, 2) void gemm_tf32(
    const float* __restrict__ A, const float* __restrict__ Bt,
    const float* __restrict__ bias, const float* __restrict__ Rsd,
    float* __restrict__ C, int M, int N, int K)
{
    extern __shared__ float smem[];
    __shared__ __align__(8) unsigned long long s_mbar[2*NSTG];  // full[0..2], empty[0..2]

    const int t = threadIdx.x, lane = t & 31, warp = t >> 5;
    const int wm = warp >> 2, wn = warp & 3;       // 2x4 warp grid, 64x32 tiles
    const int bm0 = blockIdx.y * GBM, bn0 = blockIdx.x * GBN;

    const uint32_t mb = (uint32_t)__cvta_generic_to_shared(s_mbar);
    auto fullb  = [&](int s) { return mb + 8u * s; };
    auto emptyb = [&](int s) { return mb + 8u * (NSTG + s); };

    if (t == 0) {
        #pragma unroll
        for (int s = 0; s < NSTG; s++) {
            mbar_init(fullb(s), 256);   // one noinc cp-arrive per thread per fill
            mbar_init(emptyb(s), 8);    // one arrive per warp per consume
        }
    }
    __syncthreads();

    // producers: 2 threads per row, 4 x 16B chunks each, for both A and B
    const int prow = t >> 1;                         // 0..127
    const float* Ag = A  + (size_t)(bm0 + prow) * K;
    const float* Bg = Bt + (size_t)(bn0 + prow) * K;
    const int pxr = (prow & 7) * 16;

    const uint32_t as_u = (uint32_t)__cvta_generic_to_shared(smem);
    const uint32_t bs_u = as_u + NSTG * A_STAGE * 4;
    const uint32_t a_dst = as_u + (uint32_t)prow * 128;
    const uint32_t b_dst = bs_u + (uint32_t)prow * 128;

    // ldmatrix geometry
    const int lrow = (lane & 7) + ((lane >> 3) & 1) * 8;
    const int halfB16 = ((lane >> 4) & 1) * 16;
    const int xrr = (lane & 7) * 16;
    const uint32_t a_rd = as_u + (uint32_t)((wm * 64 + lrow) * 128);
    const uint32_t b_rd = bs_u + (uint32_t)((wn * 32 + lrow) * 128);

    float acc[4][4][4];
    #pragma unroll
    for (int i = 0; i < 4; i++)
        #pragma unroll
        for (int j = 0; j < 4; j++)
            #pragma unroll
            for (int k = 0; k < 4; k++) acc[i][j][k] = 0.f;

    auto cp_stage = [&](int kt, int st) {
        const float* as = Ag + (size_t)kt * GBK;
        const float* bs = Bg + (size_t)kt * GBK;
        uint32_t soff = (uint32_t)st * (A_STAGE * 4);
        #pragma unroll
        for (int u = 0; u < 4; u++) {
            int c = (t & 1) + 2 * u;
            uint32_t off = (uint32_t)((c * 16) ^ pxr);
            cp16(a_dst + soff + off, as + c * 4);
            cp16(b_dst + soff + off, bs + c * 4);
        }
        cp_arrive(fullb(st));
    };
    auto compute = [&](int st) {
        uint32_t ab = a_rd + (uint32_t)st * (A_STAGE * 4);
        uint32_t bb = b_rd + (uint32_t)st * (B_STAGE * 4);
        #pragma unroll
        for (int kk = 0; kk < 4; kk++) {
            uint32_t ak = (uint32_t)((kk * 32 + halfB16) ^ xrr);
            uint32_t afr[4][4];
            #pragma unroll
            for (int ms = 0; ms < 4; ms++)
                ldsm4(afr[ms][0], afr[ms][1], afr[ms][2], afr[ms][3],
                      ab + (uint32_t)(ms * 16 * 128) + ak);
            uint32_t bfr[4][2];
            #pragma unroll
            for (int p = 0; p < 2; p++) {
                uint32_t r0, r1, r2, r3;
                ldsm4(r0, r1, r2, r3, bb + (uint32_t)(p * 16 * 128) + ak);
                bfr[2*p][0] = r0; bfr[2*p][1] = r2;
                bfr[2*p+1][0] = r1; bfr[2*p+1][1] = r3;
            }
            #pragma unroll
            for (int ms = 0; ms < 4; ms++)
                #pragma unroll
                for (int nt = 0; nt < 4; nt++)
                    mma_tf32(acc[ms][nt], afr[ms], bfr[nt]);
        }
    };

    const int KT = K / GBK;
    cp_stage(0, 0);
    cp_stage(1, 1);
    for (int kt = 0; kt < KT; kt++) {
        int s = kt % NSTG;
        mbar_wait_acq(fullb(s), (uint32_t)((kt / NSTG) & 1));
        compute(s);
        if (lane == 0) mbar_arrive(emptyb(s));
        int kn = kt + 2;
        if (kn < KT) {
            int s2 = kn % NSTG;
            mbar_wait_rlx(emptyb(s2), (uint32_t)(1 ^ ((kn / NSTG) & 1)));
            cp_stage(kn, s2);
        }
    }

    #pragma unroll
    for (int ms = 0; ms < 4; ms++) {
        int r0 = bm0 + wm*64 + ms*16 + (lane >> 2);
        #pragma unroll
        for (int nt = 0; nt < 4; nt++) {
            int c0 = bn0 + wn*32 + nt*8 + (lane & 3)*2;
            float2 bv = *reinterpret_cast<const float2*>(&bias[c0]);
            float2 o0, o1;
            o0.x = acc[ms][nt][0] + bv.x;  o0.y = acc[ms][nt][1] + bv.y;
            o1.x = acc[ms][nt][2] + bv.x;  o1.y = acc[ms][nt][3] + bv.y;
            if (RES) {
                float2 v0 = *reinterpret_cast<const float2*>(&Rsd[(size_t)r0 * N + c0]);
                float2 v1 = *reinterpret_cast<const float2*>(&Rsd[(size_t)(r0+8) * N + c0]);
                o0.x += v0.x; o0.y += v0.y;  o1.x += v1.x; o1.y += v1.y;
            }
            if (RND) {
                o0.x = f2tf_f(o0.x); o0.y = f2tf_f(o0.y);
                o1.x = f2tf_f(o1.x); o1.y = f2tf_f(o1.y);
            }
            *reinterpret_cast<float2*>(&C[(size_t)r0 * N + c0]) = o0;
            *reinterpret_cast<float2*>(&C[(size_t)(r0+8) * N + c0]) = o1;
        }
    }
}

// ---------------- window attention ----------------
#define APAD 68
#define ATTN_SMEM (4*64*APAD*4)

template <bool SHIFTED>
__global__ __launch_bounds__(256) void attn_kernel(const float* __restrict__ qkv,
                                                   float* __restrict__ out)
{
    extern __shared__ float sm[];
    float* Qst = sm;
    float* Kst = Qst + 64*APAD;
    float* Vs  = Kst + 64*APAD;
    float* Pt  = Vs  + 64*APAD;
    __shared__ int tok[64];
    __shared__ int rid[64];

    const int h  = blockIdx.x;
    const int wb = blockIdx.y;
    const int t  = threadIdx.x;
    const int b = wb >> 6, win = wb & 63;
    const int wr = win >> 3, wc = win & 7;

    if (t < 64) {
        int r = wr*8 + (t >> 3), c = wc*8 + (t & 7);
        int rr = r, cc = c;
        if (SHIFTED) { rr = (r + 4) & 63; cc = (c + 4) & 63; }
        tok[t] = b * NTOK + rr * GRID_S + cc;
        if (SHIFTED) {
            int fr = (r < 56) ? 0 : ((r < 60) ? 1 : 2);
            int fc = (c < 56) ? 0 : ((c < 60) ? 1 : 2);
            rid[t] = fr * 3 + fc;
        }
    }
    __syncthreads();

    {
        int l = t >> 2, d0 = (t & 3) * 16;
        const float* bp = qkv + (size_t)tok[l] * (3*DIM) + h * DHEAD;
        #pragma unroll
        for (int u = 0; u < 4; u++) {
            int d = d0 + u*4;
            float4 q4 = *reinterpret_cast<const float4*>(bp + d);
            float4 k4 = *reinterpret_cast<const float4*>(bp + DIM + d);
            float4 v4 = *reinterpret_cast<const float4*>(bp + 2*DIM + d);
            Qst[(d+0)*APAD + l] = q4.x; Qst[(d+1)*APAD + l] = q4.y;
            Qst[(d+2)*APAD + l] = q4.z; Qst[(d+3)*APAD + l] = q4.w;
            Kst[(d+0)*APAD + l] = k4.x; Kst[(d+1)*APAD + l] = k4.y;
            Kst[(d+2)*APAD + l] = k4.z; Kst[(d+3)*APAD + l] = k4.w;
            *reinterpret_cast<float4*>(&Vs[l*APAD + d]) = v4;
        }
    }
    __syncthreads();

    {
        int i0 = (t >> 4) * 4, j0 = (t & 15) * 4;
        float a[4][4];
        #pragma unroll
        for (int i = 0; i < 4; i++)
            #pragma unroll
            for (int j = 0; j < 4; j++) a[i][j] = 0.f;
        #pragma unroll 8
        for (int d = 0; d < 64; d++) {
            float4 qv = *reinterpret_cast<const float4*>(&Qst[d*APAD + i0]);
            float4 kv = *reinterpret_cast<const float4*>(&Kst[d*APAD + j0]);
            float qa[4] = { qv.x, qv.y, qv.z, qv.w };
            float ka[4] = { kv.x, kv.y, kv.z, kv.w };
            #pragma unroll
            for (int i = 0; i < 4; i++)
                #pragma unroll
                for (int j = 0; j < 4; j++)
                    a[i][j] = fmaf(qa[i], ka[j], a[i][j]);
        }
        #pragma unroll
        for (int jj = 0; jj < 4; jj++) {
            float4 o;
            float* op = &o.x;
            #pragma unroll
            for (int ii = 0; ii < 4; ii++) {
                float s = a[ii][jj] * 0.125f;
                if (SHIFTED && (rid[i0+ii] != rid[j0+jj])) s = -1e9f;
                op[ii] = s;
            }
            *reinterpret_cast<float4*>(&Pt[(j0+jj)*APAD + i0]) = o;
        }
    }
    __syncthreads();

    if (t < 64) {
        float m = -1e30f;
        #pragma unroll 8
        for (int j = 0; j < 64; j++) m = fmaxf(m, Pt[j*APAD + t]);
        float s = 0.f;
        #pragma unroll 8
        for (int j = 0; j < 64; j++) {
            float e = __expf(Pt[j*APAD + t] - m);
            Pt[j*APAD + t] = e;
            s += e;
        }
        float inv = 1.0f / s;
        #pragma unroll 8
        for (int j = 0; j < 64; j++) Pt[j*APAD + t] *= inv;
    }
    __syncthreads();

    {
        int i0 = (t >> 4) * 4, d0 = (t & 15) * 4;
        float a[4][4];
        #pragma unroll
        for (int i = 0; i < 4; i++)
            #pragma unroll
            for (int d = 0; d < 4; d++) a[i][d] = 0.f;
        #pragma unroll 8
        for (int j = 0; j < 64; j++) {
            float4 pv = *reinterpret_cast<const float4*>(&Pt[j*APAD + i0]);
            float4 vv = *reinterpret_cast<const float4*>(&Vs[j*APAD + d0]);
            float pa[4] = { pv.x, pv.y, pv.z, pv.w };
            float va[4] = { vv.x, vv.y, vv.z, vv.w };
            #pragma unroll
            for (int i = 0; i < 4; i++)
                #pragma unroll
                for (int d = 0; d < 4; d++)
                    a[i][d] = fmaf(pa[i], va[d], a[i][d]);
        }
        #pragma unroll
        for (int ii = 0; ii < 4; ii++) {
            float4 o = { f2tf_f(a[ii][0]), f2tf_f(a[ii][1]), f2tf_f(a[ii][2]), f2tf_f(a[ii][3]) };
            *reinterpret_cast<float4*>(&out[(size_t)tok[i0+ii]*DIM + h*DHEAD + d0]) = o;
        }
    }
}

// ---------------- host launch ----------------
static void run_gemm(const float* A, const float* Bt, const float* bias,
                     const float* Rsd, float* C, int M, int N, int K, bool rnd)
{
    dim3 grid(N / GBN, M / GBM);
    if (Rsd) {
        gemm_tf32<true, false><<<grid, 256, GEMM_SMEM>>>(A, Bt, bias, Rsd, C, M, N, K);
    } else {
        if (rnd) gemm_tf32<false, true ><<<grid, 256, GEMM_SMEM>>>(A, Bt, bias, A, C, M, N, K);
        else     gemm_tf32<false, false><<<grid, 256, GEMM_SMEM>>>(A, Bt, bias, A, C, M, N, K);
    }
}

extern "C" void kernel_launch(void* const* d_in, const int* in_sizes, int n_in,
                              void* d_out, int out_size)
{
    const float* x      = (const float*)d_in[0];
    const float* ln1g   = (const float*)d_in[1];
    const float* ln1b   = (const float*)d_in[2];
    const float* ln2g   = (const float*)d_in[3];
    const float* ln2b   = (const float*)d_in[4];
    const float* ln3g   = (const float*)d_in[5];
    const float* ln3b   = (const float*)d_in[6];
    const float* ln4g   = (const float*)d_in[7];
    const float* ln4b   = (const float*)d_in[8];
    const float* m1aw   = (const float*)d_in[9];
    const float* m1ab   = (const float*)d_in[10];
    const float* m2aw   = (const float*)d_in[11];
    const float* m2ab   = (const float*)d_in[12];
    const float* m1bw   = (const float*)d_in[13];
    const float* m1bb   = (const float*)d_in[14];
    const float* m2bw   = (const float*)d_in[15];
    const float* m2bb   = (const float*)d_in[16];
    const float* a1qkvw = (const float*)d_in[17];
    const float* a1qkvb = (const float*)d_in[18];
    const float* a1ow   = (const float*)d_in[19];
    const float* a1ob   = (const float*)d_in[20];
    const float* a2qkvw = (const float*)d_in[21];
    const float* a2qkvb = (const float*)d_in[22];
    const float* a2ow   = (const float*)d_in[23];
    const float* a2ob   = (const float*)d_in[24];
    float* out = (float*)d_out;

    float *nrm, *qkv, *att, *res, *out1, *hid, *wt;
    cudaGetSymbolAddress((void**)&nrm,  g_norm);
    cudaGetSymbolAddress((void**)&qkv,  g_qkv);
    cudaGetSymbolAddress((void**)&att,  g_attn);
    cudaGetSymbolAddress((void**)&res,  g_res);
    cudaGetSymbolAddress((void**)&out1, g_out1);
    cudaGetSymbolAddress((void**)&hid,  g_hid);
    cudaGetSymbolAddress((void**)&wt,   g_wt);

    cudaFuncSetAttribute(gemm_tf32<true,false>,  cudaFuncAttributeMaxDynamicSharedMemorySize, GEMM_SMEM);
    cudaFuncSetAttribute(gemm_tf32<false,true>,  cudaFuncAttributeMaxDynamicSharedMemorySize, GEMM_SMEM);
    cudaFuncSetAttribute(gemm_tf32<false,false>, cudaFuncAttributeMaxDynamicSharedMemorySize, GEMM_SMEM);
    cudaFuncSetAttribute(attn_kernel<false>, cudaFuncAttributeMaxDynamicSharedMemorySize, ATTN_SMEM);
    cudaFuncSetAttribute(attn_kernel<true>,  cudaFuncAttributeMaxDynamicSharedMemorySize, ATTN_SMEM);

    float* w1qkv = wt + OFF_QKV;
    float* w1o   = wt + OFF_WO;
    float* w1ma  = wt + OFF_MA;
    float* w1mb  = wt + OFF_MB;
    float* w2qkv = wt + LAYER_W + OFF_QKV;
    float* w2o   = wt + LAYER_W + OFF_WO;
    float* w2ma  = wt + LAYER_W + OFF_MA;
    float* w2mb  = wt + LAYER_W + OFF_MB;

    TransArgs ta;
    auto tiles = [](int K, int N) { return (K / 32) * (N / 32); };
    int t0 = 0;
    const float* srcs[8] = { a1qkvw, a1ow, m1aw, m1bw, a2qkvw, a2ow, m2aw, m2bw };
    float*       dsts[8] = { w1qkv,  w1o,  w1ma, w1mb, w2qkv,  w2o,  w2ma, w2mb };
    int Ks[8] = { DIM, DIM, DIM, 4*DIM, DIM, DIM, DIM, 4*DIM };
    int Ns[8] = { 3*DIM, DIM, 4*DIM, DIM, 3*DIM, DIM, 4*DIM, DIM };
    for (int i = 0; i < 8; i++) {
        ta.w[i].s = srcs[i]; ta.w[i].d = dsts[i];
        ta.w[i].K = Ks[i];   ta.w[i].N = Ns[i];
        ta.w[i].t0 = t0;     t0 += tiles(Ks[i], Ns[i]);
    }

    dummy_k<<<1, 32>>>(qkv);              // launch 1
    trans_tf32<<<t0, 256>>>(ta);          // launch 2

    // ---- layer 1: W-MSA ----
    ln_kernel<<<ROWS, 256>>>(x, ln1g, ln1b, nrm);                          // 3
    run_gemm(nrm, w1qkv, a1qkvb, nullptr, qkv, ROWS, 3*DIM, DIM, false);   // 4 <- profiled
    attn_kernel<false><<<dim3(NHEAD, BSZ*64), 256, ATTN_SMEM>>>(qkv, att);
    run_gemm(att, w1o, a1ob, nrm, res, ROWS, DIM, DIM, false);
    // ---- layer 1: MLP ----
    ln_kernel<<<ROWS, 256>>>(res, ln2g, ln2b, nrm);
    run_gemm(nrm, w1ma, m1ab, nullptr, hid, ROWS, 4*DIM, DIM, true);
    run_gemm(hid, w1mb, m1bb, res, out1, ROWS, DIM, 4*DIM, false);
    // ---- layer 2: SW-MSA ----
    ln_kernel<<<ROWS, 256>>>(out1, ln3g, ln3b, nrm);
    run_gemm(nrm, w2qkv, a2qkvb, nullptr, qkv, ROWS, 3*DIM, DIM, false);
    attn_kernel<true><<<dim3(NHEAD, BSZ*64), 256, ATTN_SMEM>>>(qkv, att);
    run_gemm(att, w2o, a2ob, out1, res, ROWS, DIM, DIM, false);
    // ---- layer 2: MLP ----
    ln_kernel<<<ROWS, 256>>>(res, ln4g, ln4b, nrm);
    run_gemm(nrm, w2ma, m2ab, nullptr, hid, ROWS, 4*DIM, DIM, true);
    run_gemm(hid, w2mb, m2bb, res, out, ROWS, DIM, 4*DIM, false);
}

// round 12
// speedup vs baseline: 2.0181x; 2.0181x over previous
#include <cuda_runtime.h>
#include <cuda_fp16.h>
#include <cstdint>
#include <cstddef>

#define BSZ    4
#define GRID_S 64
#define DIM    1024
#define NHEAD  16
#define DHEAD  64
#define NTOK   4096
#define ROWS   (BSZ*NTOK)

// ---------------- scratch ----------------
__device__ __align__(256) __half g_normh[(size_t)ROWS*DIM];
__device__ __align__(256) __half g_qkvh [(size_t)ROWS*3*DIM];
__device__ __align__(256) __half g_attnh[(size_t)ROWS*DIM];
__device__ __align__(256) __half g_hidh [(size_t)ROWS*4*DIM];
__device__ __align__(256) float  g_res [(size_t)ROWS*DIM];
__device__ __align__(256) float  g_out1[(size_t)ROWS*DIM];
__device__ __align__(256) __half g_wth [25165824];   // fp16, TRANSPOSED [N][K]

#define OFF_QKV 0
#define OFF_WO  3145728
#define OFF_MA  4194304
#define OFF_MB  8388608
#define LAYER_W 12582912

// ---------------- dummy (profiler alignment: ncu captures 4th launch) ----------------
__global__ void dummy_k(float* p) { if (threadIdx.x == 0) p[0] = 0.f; }

// ---------------- fused transpose + fp16 convert for all 8 weights ----------------
struct TransDesc { const float* s; __half* d; int K; int N; int t0; };
struct TransArgs { TransDesc w[8]; };

__global__ __launch_bounds__(256) void trans_h(TransArgs a)
{
    __shared__ float sm[32][33];
    int bid = blockIdx.x;
    int seg = 0;
    #pragma unroll
    for (int i = 1; i < 8; i++) if (bid >= a.w[i].t0) seg = i;
    const float* src = a.w[seg].s;
    __half* dst = a.w[seg].d;
    int K = a.w[seg].K, N = a.w[seg].N;
    int local = bid - a.w[seg].t0;
    int ncols = N >> 5;
    int tr = local / ncols, tc = local - tr * ncols;
    int t = threadIdx.x;
    int r0 = t >> 5, c = t & 31;
    #pragma unroll
    for (int u = 0; u < 4; u++) {
        int k = tr * 32 + r0 + u * 8;
        sm[r0 + u * 8][c] = src[(size_t)k * N + tc * 32 + c];
    }
    __syncthreads();
    #pragma unroll
    for (int u = 0; u < 4; u++) {
        int n = tc * 32 + r0 + u * 8;
        dst[(size_t)n * K + tr * 32 + c] = __float2half_rn(sm[c][r0 + u * 8]);
    }
}

// ---------------- LayerNorm (fp32 in, fp16 out) ----------------
__global__ __launch_bounds__(256) void ln_kernel(const float* __restrict__ x,
                                                 const float* __restrict__ g,
                                                 const float* __restrict__ b,
                                                 __half* __restrict__ y)
{
    int row = blockIdx.x, t = threadIdx.x;
    float4 v = reinterpret_cast<const float4*>(x + (size_t)row * DIM)[t];
    float s = v.x + v.y + v.z + v.w;
    float q = v.x*v.x + v.y*v.y + v.z*v.z + v.w*v.w;
    #pragma unroll
    for (int o = 16; o > 0; o >>= 1) {
        s += __shfl_xor_sync(0xffffffffu, s, o);
        q += __shfl_xor_sync(0xffffffffu, q, o);
    }
    __shared__ float rs_[8], rq_[8];
    __shared__ float s_mu, s_rs;
    if ((t & 31) == 0) { rs_[t>>5] = s; rq_[t>>5] = q; }
    __syncthreads();
    if (t == 0) {
        float S = 0.f, Q = 0.f;
        #pragma unroll
        for (int i = 0; i < 8; i++) { S += rs_[i]; Q += rq_[i]; }
        float mu = S * (1.0f/DIM);
        s_mu = mu;
        s_rs = rsqrtf(Q * (1.0f/DIM) - mu*mu + 1e-5f);
    }
    __syncthreads();
    float mu = s_mu, r = s_rs;
    float4 g4 = reinterpret_cast<const float4*>(g)[t];
    float4 b4 = reinterpret_cast<const float4*>(b)[t];
    float ox = (v.x-mu)*r*g4.x + b4.x;
    float oy = (v.y-mu)*r*g4.y + b4.y;
    float oz = (v.z-mu)*r*g4.z + b4.z;
    float ow = (v.w-mu)*r*g4.w + b4.w;
    __half* yp = y + (size_t)row * DIM + t * 4;
    *reinterpret_cast<__half2*>(yp)     = __floats2half2_rn(ox, oy);
    *reinterpret_cast<__half2*>(yp + 2) = __floats2half2_rn(oz, ow);
}

// ---------------- FP16 GEMM v12: 128x128 tile, 64x32 warp tile, GBK=64 halves, 3-stage, 2 CTAs/SM ----------------
#define GBM 128
#define GBN 128
#define GBKH 64                          // halves per k-tile (128 bytes per row)
#define STAGE_BYTES (128*128)            // 16KB per operand per stage
#define NSTG 3
#define GEMM_SMEM (NSTG*2*STAGE_BYTES)   // 96KB -> 2 CTAs/SM

__device__ __forceinline__ void ldsm4(uint32_t& r0, uint32_t& r1, uint32_t& r2, uint32_t& r3, uint32_t a) {
    asm volatile("ldmatrix.sync.aligned.m8n8.x4.shared.b16 {%0,%1,%2,%3}, [%4];"
                 : "=r"(r0), "=r"(r1), "=r"(r2), "=r"(r3) : "r"(a));
}
__device__ __forceinline__ void mma_fp16(float* c, const uint32_t* a, const uint32_t* b) {
    asm volatile("mma.sync.aligned.m16n8k16.row.col.f32.f16.f16.f32 "
                 "{%0,%1,%2,%3}, {%4,%5,%6,%7}, {%8,%9}, {%0,%1,%2,%3};"
                 : "+f"(c[0]), "+f"(c[1]), "+f"(c[2]), "+f"(c[3])
                 : "r"(a[0]), "r"(a[1]), "r"(a[2]), "r"(a[3]), "r"(b[0]), "r"(b[1]));
}
__device__ __forceinline__ void cp16(uint32_t dst, const void* src) {
    asm volatile("cp.async.cg.shared.global [%0], [%1], 16;" :: "r"(dst), "l"(src));
}

// MODE: 0 = no residual, fp16 out; 1 = fp32 residual, fp32 out; 2 = fp16 residual, fp32 out
template <int MODE>
__global__ __launch_bounds__(256, 2) void gemm_fp16k(
    const __half* __restrict__ A, const __half* __restrict__ Bt,
    const float* __restrict__ bias, const void* __restrict__ Rsd,
    void* __restrict__ Cv, int M, int N, int K)
{
    extern __shared__ char smem[];
    const int t = threadIdx.x, lane = t & 31, warp = t >> 5;
    const int wm = warp >> 2, wn = warp & 3;       // 2x4 warp grid, 64x32 tiles
    const int bm0 = blockIdx.y * GBM, bn0 = blockIdx.x * GBN;

    // producers: 2 threads per row, 4 x 16B chunks each (128B row = 64 halves)
    const int prow = t >> 1;
    const __half* Ag = A  + (size_t)(bm0 + prow) * K;
    const __half* Bg = Bt + (size_t)(bn0 + prow) * K;
    const int pxr = (prow & 7) * 16;

    const uint32_t as_u = (uint32_t)__cvta_generic_to_shared(smem);
    const uint32_t bs_u = as_u + NSTG * STAGE_BYTES;
    const uint32_t a_dst = as_u + (uint32_t)prow * 128;
    const uint32_t b_dst = bs_u + (uint32_t)prow * 128;

    // ldmatrix geometry (byte-identical to the tf32 version)
    const int lrow = (lane & 7) + ((lane >> 3) & 1) * 8;
    const int halfB16 = ((lane >> 4) & 1) * 16;
    const int xrr = (lane & 7) * 16;
    const uint32_t a_rd = as_u + (uint32_t)((wm * 64 + lrow) * 128);
    const uint32_t b_rd = bs_u + (uint32_t)((wn * 32 + lrow) * 128);

    float acc[4][4][4];
    #pragma unroll
    for (int i = 0; i < 4; i++)
        #pragma unroll
        for (int j = 0; j < 4; j++)
            #pragma unroll
            for (int k = 0; k < 4; k++) acc[i][j][k] = 0.f;

    auto cp_stage = [&](int kt, int st) {
        const __half* as = Ag + (size_t)kt * GBKH;
        const __half* bs = Bg + (size_t)kt * GBKH;
        uint32_t soff = (uint32_t)st * STAGE_BYTES;
        #pragma unroll
        for (int u = 0; u < 4; u++) {
            int c = (t & 1) + 2 * u;
            uint32_t off = (uint32_t)((c * 16) ^ pxr);
            cp16(a_dst + soff + off, as + c * 8);
            cp16(b_dst + soff + off, bs + c * 8);
        }
        asm volatile("cp.async.commit_group;");
    };
    auto compute = [&](int st) {
        uint32_t ab = a_rd + (uint32_t)st * STAGE_BYTES;
        uint32_t bb = b_rd + (uint32_t)st * STAGE_BYTES;
        #pragma unroll
        for (int kk = 0; kk < 4; kk++) {            // 4 x (K=16) per 64-half tile
            uint32_t ak = (uint32_t)((kk * 32 + halfB16) ^ xrr);
            uint32_t afr[4][4];
            #pragma unroll
            for (int ms = 0; ms < 4; ms++)
                ldsm4(afr[ms][0], afr[ms][1], afr[ms][2], afr[ms][3],
                      ab + (uint32_t)(ms * 16 * 128) + ak);
            uint32_t bfr[4][2];
            #pragma unroll
            for (int p = 0; p < 2; p++) {
                uint32_t r0, r1, r2, r3;
                ldsm4(r0, r1, r2, r3, bb + (uint32_t)(p * 16 * 128) + ak);
                bfr[2*p][0] = r0; bfr[2*p][1] = r2;
                bfr[2*p+1][0] = r1; bfr[2*p+1][1] = r3;
            }
            #pragma unroll
            for (int ms = 0; ms < 4; ms++)
                #pragma unroll
                for (int nt = 0; nt < 4; nt++)
                    mma_fp16(acc[ms][nt], afr[ms], bfr[nt]);
        }
    };

    const int KT = K / GBKH;
    cp_stage(0, 0);
    cp_stage(1, 1);
    int sw = 2;
    for (int kt = 0; kt < KT; kt++) {
        if (kt < KT - 1) asm volatile("cp.async.wait_group 1;");
        else             asm volatile("cp.async.wait_group 0;");
        __syncthreads();
        if (kt + 2 < KT) {
            cp_stage(kt + 2, sw);
            if (++sw == NSTG) sw = 0;
        }
        compute(kt % NSTG);
    }

    #pragma unroll
    for (int ms = 0; ms < 4; ms++) {
        int r0 = bm0 + wm*64 + ms*16 + (lane >> 2);
        #pragma unroll
        for (int nt = 0; nt < 4; nt++) {
            int c0 = bn0 + wn*32 + nt*8 + (lane & 3)*2;
            float2 bv = *reinterpret_cast<const float2*>(&bias[c0]);
            float2 o0, o1;
            o0.x = acc[ms][nt][0] + bv.x;  o0.y = acc[ms][nt][1] + bv.y;
            o1.x = acc[ms][nt][2] + bv.x;  o1.y = acc[ms][nt][3] + bv.y;
            if (MODE == 1) {
                const float* R = (const float*)Rsd;
                float2 v0 = *reinterpret_cast<const float2*>(&R[(size_t)r0 * N + c0]);
                float2 v1 = *reinterpret_cast<const float2*>(&R[(size_t)(r0+8) * N + c0]);
                o0.x += v0.x; o0.y += v0.y;  o1.x += v1.x; o1.y += v1.y;
            } else if (MODE == 2) {
                const __half* R = (const __half*)Rsd;
                float2 v0 = __half22float2(*reinterpret_cast<const __half2*>(&R[(size_t)r0 * N + c0]));
                float2 v1 = __half22float2(*reinterpret_cast<const __half2*>(&R[(size_t)(r0+8) * N + c0]));
                o0.x += v0.x; o0.y += v0.y;  o1.x += v1.x; o1.y += v1.y;
            }
            if (MODE == 0) {
                __half* Co = (__half*)Cv;
                *reinterpret_cast<__half2*>(&Co[(size_t)r0 * N + c0])     = __floats2half2_rn(o0.x, o0.y);
                *reinterpret_cast<__half2*>(&Co[(size_t)(r0+8) * N + c0]) = __floats2half2_rn(o1.x, o1.y);
            } else {
                float* Co = (float*)Cv;
                *reinterpret_cast<float2*>(&Co[(size_t)r0 * N + c0]) = o0;
                *reinterpret_cast<float2*>(&Co[(size_t)(r0+8) * N + c0]) = o1;
            }
        }
    }
}

// ---------------- window attention (fp16 in/out, fp32 math) ----------------
#define APAD 68
#define ATTN_SMEM (4*64*APAD*4)

template <bool SHIFTED>
__global__ __launch_bounds__(256) void attn_kernel(const __half* __restrict__ qkv,
                                                   __half* __restrict__ out)
{
    extern __shared__ float sm[];
    float* Qst = sm;
    float* Kst = Qst + 64*APAD;
    float* Vs  = Kst + 64*APAD;
    float* Pt  = Vs  + 64*APAD;
    __shared__ int tok[64];
    __shared__ int rid[64];

    const int h  = blockIdx.x;
    const int wb = blockIdx.y;
    const int t  = threadIdx.x;
    const int b = wb >> 6, win = wb & 63;
    const int wr = win >> 3, wc = win & 7;

    if (t < 64) {
        int r = wr*8 + (t >> 3), c = wc*8 + (t & 7);
        int rr = r, cc = c;
        if (SHIFTED) { rr = (r + 4) & 63; cc = (c + 4) & 63; }
        tok[t] = b * NTOK + rr * GRID_S + cc;
        if (SHIFTED) {
            int fr = (r < 56) ? 0 : ((r < 60) ? 1 : 2);
            int fc = (c < 56) ? 0 : ((c < 60) ? 1 : 2);
            rid[t] = fr * 3 + fc;
        }
    }
    __syncthreads();

    {
        int l = t >> 2, d0 = (t & 3) * 16;
        const __half* bp = qkv + (size_t)tok[l] * (3*DIM) + h * DHEAD;
        #pragma unroll
        for (int u = 0; u < 2; u++) {
            int d = d0 + u*8;
            float4 qr = *reinterpret_cast<const float4*>(bp + d);
            float4 kr = *reinterpret_cast<const float4*>(bp + DIM + d);
            float4 vr = *reinterpret_cast<const float4*>(bp + 2*DIM + d);
            const __half2* qh = reinterpret_cast<const __half2*>(&qr);
            const __half2* kh = reinterpret_cast<const __half2*>(&kr);
            const __half2* vh = reinterpret_cast<const __half2*>(&vr);
            #pragma unroll
            for (int j = 0; j < 4; j++) {
                float2 qf = __half22float2(qh[j]);
                float2 kf = __half22float2(kh[j]);
                float2 vf = __half22float2(vh[j]);
                Qst[(d + 2*j    )*APAD + l] = qf.x;
                Qst[(d + 2*j + 1)*APAD + l] = qf.y;
                Kst[(d + 2*j    )*APAD + l] = kf.x;
                Kst[(d + 2*j + 1)*APAD + l] = kf.y;
                Vs[l*APAD + d + 2*j    ] = vf.x;
                Vs[l*APAD + d + 2*j + 1] = vf.y;
            }
        }
    }
    __syncthreads();

    {
        int i0 = (t >> 4) * 4, j0 = (t & 15) * 4;
        float a[4][4];
        #pragma unroll
        for (int i = 0; i < 4; i++)
            #pragma unroll
            for (int j = 0; j < 4; j++) a[i][j] = 0.f;
        #pragma unroll 8
        for (int d = 0; d < 64; d++) {
            float4 qv = *reinterpret_cast<const float4*>(&Qst[d*APAD + i0]);
            float4 kv = *reinterpret_cast<const float4*>(&Kst[d*APAD + j0]);
            float qa[4] = { qv.x, qv.y, qv.z, qv.w };
            float ka[4] = { kv.x, kv.y, kv.z, kv.w };
            #pragma unroll
            for (int i = 0; i < 4; i++)
                #pragma unroll
                for (int j = 0; j < 4; j++)
                    a[i][j] = fmaf(qa[i], ka[j], a[i][j]);
        }
        #pragma unroll
        for (int jj = 0; jj < 4; jj++) {
            float4 o;
            float* op = &o.x;
            #pragma unroll
            for (int ii = 0; ii < 4; ii++) {
                float s = a[ii][jj] * 0.125f;
                if (SHIFTED && (rid[i0+ii] != rid[j0+jj])) s = -1e9f;
                op[ii] = s;
            }
            *reinterpret_cast<float4*>(&Pt[(j0+jj)*APAD + i0]) = o;
        }
    }
    __syncthreads();

    if (t < 64) {
        float m = -1e30f;
        #pragma unroll 8
        for (int j = 0; j < 64; j++) m = fmaxf(m, Pt[j*APAD + t]);
        float s = 0.f;
        #pragma unroll 8
        for (int j = 0; j < 64; j++) {
            float e = __expf(Pt[j*APAD + t] - m);
            Pt[j*APAD + t] = e;
            s += e;
        }
        float inv = 1.0f / s;
        #pragma unroll 8
        for (int j = 0; j < 64; j++) Pt[j*APAD + t] *= inv;
    }
    __syncthreads();

    {
        int i0 = (t >> 4) * 4, d0 = (t & 15) * 4;
        float a[4][4];
        #pragma unroll
        for (int i = 0; i < 4; i++)
            #pragma unroll
            for (int d = 0; d < 4; d++) a[i][d] = 0.f;
        #pragma unroll 8
        for (int j = 0; j < 64; j++) {
            float4 pv = *reinterpret_cast<const float4*>(&Pt[j*APAD + i0]);
            float4 vv = *reinterpret_cast<const float4*>(&Vs[j*APAD + d0]);
            float pa[4] = { pv.x, pv.y, pv.z, pv.w };
            float va[4] = { vv.x, vv.y, vv.z, vv.w };
            #pragma unroll
            for (int i = 0; i < 4; i++)
                #pragma unroll
                for (int d = 0; d < 4; d++)
                    a[i][d] = fmaf(pa[i], va[d], a[i][d]);
        }
        #pragma unroll
        for (int ii = 0; ii < 4; ii++) {
            __half* op = out + (size_t)tok[i0+ii]*DIM + h*DHEAD + d0;
            *reinterpret_cast<__half2*>(op)     = __floats2half2_rn(a[ii][0], a[ii][1]);
            *reinterpret_cast<__half2*>(op + 2) = __floats2half2_rn(a[ii][2], a[ii][3]);
        }
    }
}

// ---------------- host launch ----------------
extern "C" void kernel_launch(void* const* d_in, const int* in_sizes, int n_in,
                              void* d_out, int out_size)
{
    const float* x      = (const float*)d_in[0];
    const float* ln1g   = (const float*)d_in[1];
    const float* ln1b   = (const float*)d_in[2];
    const float* ln2g   = (const float*)d_in[3];
    const float* ln2b   = (const float*)d_in[4];
    const float* ln3g   = (const float*)d_in[5];
    const float* ln3b   = (const float*)d_in[6];
    const float* ln4g   = (const float*)d_in[7];
    const float* ln4b   = (const float*)d_in[8];
    const float* m1aw   = (const float*)d_in[9];
    const float* m1ab   = (const float*)d_in[10];
    const float* m2aw   = (const float*)d_in[11];
    const float* m2ab   = (const float*)d_in[12];
    const float* m1bw   = (const float*)d_in[13];
    const float* m1bb   = (const float*)d_in[14];
    const float* m2bw   = (const float*)d_in[15];
    const float* m2bb   = (const float*)d_in[16];
    const float* a1qkvw = (const float*)d_in[17];
    const float* a1qkvb = (const float*)d_in[18];
    const float* a1ow   = (const float*)d_in[19];
    const float* a1ob   = (const float*)d_in[20];
    const float* a2qkvw = (const float*)d_in[21];
    const float* a2qkvb = (const float*)d_in[22];
    const float* a2ow   = (const float*)d_in[23];
    const float* a2ob   = (const float*)d_in[24];
    float* out = (float*)d_out;

    __half *nrm, *qkv, *att, *hid, *wt;
    float *res, *out1;
    cudaGetSymbolAddress((void**)&nrm,  g_normh);
    cudaGetSymbolAddress((void**)&qkv,  g_qkvh);
    cudaGetSymbolAddress((void**)&att,  g_attnh);
    cudaGetSymbolAddress((void**)&hid,  g_hidh);
    cudaGetSymbolAddress((void**)&res,  g_res);
    cudaGetSymbolAddress((void**)&out1, g_out1);
    cudaGetSymbolAddress((void**)&wt,   g_wth);

    cudaFuncSetAttribute(gemm_fp16k<0>, cudaFuncAttributeMaxDynamicSharedMemorySize, GEMM_SMEM);
    cudaFuncSetAttribute(gemm_fp16k<1>, cudaFuncAttributeMaxDynamicSharedMemorySize, GEMM_SMEM);
    cudaFuncSetAttribute(gemm_fp16k<2>, cudaFuncAttributeMaxDynamicSharedMemorySize, GEMM_SMEM);
    cudaFuncSetAttribute(attn_kernel<false>, cudaFuncAttributeMaxDynamicSharedMemorySize, ATTN_SMEM);
    cudaFuncSetAttribute(attn_kernel<true>,  cudaFuncAttributeMaxDynamicSharedMemorySize, ATTN_SMEM);

    __half* w1qkv = wt + OFF_QKV;
    __half* w1o   = wt + OFF_WO;
    __half* w1ma  = wt + OFF_MA;
    __half* w1mb  = wt + OFF_MB;
    __half* w2qkv = wt + LAYER_W + OFF_QKV;
    __half* w2o   = wt + LAYER_W + OFF_WO;
    __half* w2ma  = wt + LAYER_W + OFF_MA;
    __half* w2mb  = wt + LAYER_W + OFF_MB;

    TransArgs ta;
    auto tiles = [](int K, int N) { return (K / 32) * (N / 32); };
    int t0 = 0;
    const float* srcs[8] = { a1qkvw, a1ow, m1aw, m1bw, a2qkvw, a2ow, m2aw, m2bw };
    __half*      dsts[8] = { w1qkv,  w1o,  w1ma, w1mb, w2qkv,  w2o,  w2ma, w2mb };
    int Ks[8] = { DIM, DIM, DIM, 4*DIM, DIM, DIM, DIM, 4*DIM };
    int Ns[8] = { 3*DIM, DIM, 4*DIM, DIM, 3*DIM, DIM, 4*DIM, DIM };
    for (int i = 0; i < 8; i++) {
        ta.w[i].s = srcs[i]; ta.w[i].d = dsts[i];
        ta.w[i].K = Ks[i];   ta.w[i].N = Ns[i];
        ta.w[i].t0 = t0;     t0 += tiles(Ks[i], Ns[i]);
    }

    dummy_k<<<1, 32>>>(res);              // launch 1
    trans_h<<<t0, 256>>>(ta);             // launch 2

    dim3 gQKV(3*DIM / GBN, ROWS / GBM);
    dim3 gD  (DIM / GBN,   ROWS / GBM);
    dim3 gH  (4*DIM / GBN, ROWS / GBM);
    dim3 gAtt(NHEAD, BSZ*64);

    // ---- layer 1: W-MSA ----
    ln_kernel<<<ROWS, 256>>>(x, ln1g, ln1b, nrm);                                           // 3
    gemm_fp16k<0><<<gQKV, 256, GEMM_SMEM>>>(nrm, w1qkv, a1qkvb, nullptr, qkv, ROWS, 3*DIM, DIM); // 4 <- profiled
    attn_kernel<false><<<gAtt, 256, ATTN_SMEM>>>(qkv, att);
    gemm_fp16k<2><<<gD, 256, GEMM_SMEM>>>(att, w1o, a1ob, nrm, res, ROWS, DIM, DIM);        // w = inp1 + attn@Wo
    // ---- layer 1: MLP ----
    ln_kernel<<<ROWS, 256>>>(res, ln2g, ln2b, nrm);
    gemm_fp16k<0><<<gH, 256, GEMM_SMEM>>>(nrm, w1ma, m1ab, nullptr, hid, ROWS, 4*DIM, DIM);
    gemm_fp16k<1><<<gD, 256, GEMM_SMEM>>>(hid, w1mb, m1bb, res, out1, ROWS, DIM, 4*DIM);
    // ---- layer 2: SW-MSA ----
    ln_kernel<<<ROWS, 256>>>(out1, ln3g, ln3b, nrm);
    gemm_fp16k<0><<<gQKV, 256, GEMM_SMEM>>>(nrm, w2qkv, a2qkvb, nullptr, qkv, ROWS, 3*DIM, DIM);
    attn_kernel<true><<<gAtt, 256, ATTN_SMEM>>>(qkv, att);
    gemm_fp16k<1><<<gD, 256, GEMM_SMEM>>>(att, w2o, a2ob, out1, res, ROWS, DIM, DIM);       // sw = out1 + attn@Wo
    // ---- layer 2: MLP ----
    ln_kernel<<<ROWS, 256>>>(res, ln4g, ln4b, nrm);
    gemm_fp16k<0><<<gH, 256, GEMM_SMEM>>>(nrm, w2ma, m2ab, nullptr, hid, ROWS, 4*DIM, DIM);
    gemm_fp16k<1><<<gD, 256, GEMM_SMEM>>>(hid, w2mb, m2bb, res, out, ROWS, DIM, 4*DIM);
}